// round 8
// baseline (speedup 1.0000x reference)
#include <cuda_runtime.h>

#define BB 4
#define TT 256
#define DD 256
#define HH 4
#define DKK 64
#define NREL 64
#define NT (BB*TT)   // 1024

__device__ float g_q[NT*DD];
__device__ float g_k[NT*DD];
__device__ float g_v[NT*DD];
__device__ float g_agg[NT*DD];

// ---------------------------------------------------------------------------
// K1: merged QKV projection. One block: 64n x 32e tile for ALL of q,k,v,
// reusing the x tile. 128 threads, grid 16x8 = 128 (single wave).
// Fragment per weight: 4n x 4e. FMA:LDS = 192:16 per q16 iter.
// ---------------------------------------------------------------------------
__global__ void __launch_bounds__(128) qkv_kernel(
        const float* __restrict__ x,
        const float* __restrict__ Wq, const float* __restrict__ Wk,
        const float* __restrict__ Wv,
        const float* __restrict__ bq, const float* __restrict__ bk,
        const float* __restrict__ bv) {
    __shared__ float As[64*64];
    __shared__ float Bs[3][32*64];
    int n0 = blockIdx.x * 64;
    int e0 = blockIdx.y * 32;
    const float* W[3]  = {Wq, Wk, Wv};

    int t  = threadIdx.x;
    int el = t & 7;          // e = e0 + el + 8j, j=0..3
    int nl = t >> 3;         // n = n0 + nl + 16i, i=0..3
    float acc[3][4][4];
    #pragma unroll
    for (int z = 0; z < 3; z++)
        #pragma unroll
        for (int i = 0; i < 4; i++)
            #pragma unroll
            for (int j = 0; j < 4; j++) acc[z][i][j] = 0.f;

    int lrow = t >> 4;       // 0..7
    int lq   = t & 15;       // quad 0..15

    for (int d0 = 0; d0 < DD; d0 += 64) {
        __syncthreads();
        #pragma unroll
        for (int r = 0; r < 8; r++) {
            int row = lrow + 8*r;
            *(float4*)&As[row*64 + ((lq ^ (row&15))<<2)] =
                *(const float4*)&x[(n0+row)*DD + d0 + lq*4];
        }
        #pragma unroll
        for (int z = 0; z < 3; z++)
            #pragma unroll
            for (int r = 0; r < 4; r++) {
                int row = lrow + 8*r;
                *(float4*)&Bs[z][row*64 + ((lq ^ (row&15))<<2)] =
                    *(const float4*)&W[z][(e0+row)*DD + d0 + lq*4];
            }
        __syncthreads();
        #pragma unroll 16
        for (int q16 = 0; q16 < 16; q16++) {
            float4 a[4];
            #pragma unroll
            for (int i = 0; i < 4; i++) {
                int row = nl + 16*i;
                a[i] = *(const float4*)&As[row*64 + ((q16 ^ (row&15))<<2)];
            }
            #pragma unroll
            for (int z = 0; z < 3; z++) {
                float4 b[4];
                #pragma unroll
                for (int j = 0; j < 4; j++) {
                    int row = el + 8*j;
                    b[j] = *(const float4*)&Bs[z][row*64 + ((q16 ^ (row&15))<<2)];
                }
                #pragma unroll
                for (int i = 0; i < 4; i++)
                    #pragma unroll
                    for (int j = 0; j < 4; j++)
                        acc[z][i][j] += a[i].x*b[j].x + a[i].y*b[j].y
                                      + a[i].z*b[j].z + a[i].w*b[j].w;
            }
        }
    }
    {
        const float* bz[3] = {bq, bk, bv};
        float* oz[3] = {g_q, g_k, g_v};
        #pragma unroll
        for (int z = 0; z < 3; z++)
            #pragma unroll
            for (int i = 0; i < 4; i++) {
                int n = n0 + nl + 16*i;
                #pragma unroll
                for (int j = 0; j < 4; j++) {
                    int e = e0 + el + 8*j;
                    oz[z][n*DD + e] = acc[z][i][j] + bz[z][e];
                }
            }
    }
}

// ---------------------------------------------------------------------------
// K2: fused attention. One block per (b, h, 32-row i-tile), 2 passes of 16
// rows. Separate K and V smem buffers amortize tile loads. 256 threads.
// grid (8,4,4) = 128 blocks (single wave).
// ---------------------------------------------------------------------------
// layout: Ks[256*68] | Vs[256*68] | Qs[32*68] | QRs[32*68] | Ss[16*260] | Ws[32*68]
#define ATTN_SMEM_FLOATS (256*68 + 256*68 + 32*68 + 32*68 + 16*260 + 32*68)

extern __shared__ float sm[];

__global__ void __launch_bounds__(256) attn_kernel(
        const int*  __restrict__ spatial,
        const float* __restrict__ rel_k,
        const float* __restrict__ rel_v) {
    float* Ks  = sm;
    float* Vs  = Ks  + 256*68;
    float* Qs  = Vs  + 256*68;
    float* QRs = Qs  + 32*68;
    float* Ss  = QRs + 32*68;
    float* Ws  = Ss  + 16*260;

    int it = blockIdx.x, h = blockIdx.y, b = blockIdx.z;
    int i0 = it * 32;
    int t  = threadIdx.x;
    int hd = h * DKK;
    int w = t >> 5, lane = t & 31;

    // P0: Q tile [32x64] scaled by 1/8, rel_k [64x64] into Vs, zero Ws
    {
        int rr = t >> 4, q = t & 15;
        #pragma unroll
        for (int r = 0; r < 2; r++) {
            int ii = rr + 16*r;
            float4 v = *(const float4*)&g_q[(b*TT + i0 + ii)*DD + hd + q*4];
            v.x *= 0.125f; v.y *= 0.125f; v.z *= 0.125f; v.w *= 0.125f;
            *(float4*)&Qs[ii*68 + q*4] = v;
        }
        #pragma unroll
        for (int r = 0; r < 4; r++) {
            int row = rr + 16*r;
            *(float4*)&Vs[row*68 + q*4] =
                *(const float4*)&rel_k[row*DD + hd + q*4];
        }
    }
    for (int idx = t; idx < 32*68; idx += 256) Ws[idx] = 0.f;
    __syncthreads();

    // P2: qr[ii][rel] = <Q_ii, rel_k[rel]>  (32x64 outputs, 8/thread)
    #pragma unroll
    for (int rr = 0; rr < 8; rr++) {
        int o = t + 256*rr;
        int ii = o >> 6, rel = o & 63;
        float s = 0.f;
        #pragma unroll
        for (int q16 = 0; q16 < 16; q16++) {
            float4 qv = *(const float4*)&Qs[ii*68 + q16*4];
            float4 kv = *(const float4*)&Vs[rel*68 + q16*4];
            s += qv.x*kv.x + qv.y*kv.y + qv.z*kv.z + qv.w*kv.w;
        }
        QRs[ii*68 + rel] = s;
    }
    __syncthreads();   // QRs done; Vs (rel_k) free

    // load K -> Ks, V -> Vs  (16 f4 each per thread)
    {
        int q = t & 15;
        #pragma unroll
        for (int r = 0; r < 16; r++) {
            int row = (t>>4) + 16*r;
            *(float4*)&Ks[row*68 + q*4] =
                *(const float4*)&g_k[(b*TT + row)*DD + hd + q*4];
            *(float4*)&Vs[row*68 + q*4] =
                *(const float4*)&g_v[(b*TT + row)*DD + hd + q*4];
        }
    }
    __syncthreads();

    int jl = lane & 7, il = lane >> 3;
    int iy = w & 3, jh = w >> 2;
    int il2 = lane >> 4, dq = lane & 15;
    int ib = 4*iy + 2*il2;
    float a6[2][2][4];
    #pragma unroll
    for (int p = 0; p < 2; p++)
        #pragma unroll
        for (int r = 0; r < 2; r++)
            #pragma unroll
            for (int c = 0; c < 4; c++) a6[p][r][c] = 0.f;

    for (int p = 0; p < 2; p++) {
        int rb = p * 16;
        // scores: warp w owns j in [32w,32w+32); i = il+4r, j = 32w+jl+8c
        {
            float s[4][4];
            #pragma unroll
            for (int r = 0; r < 4; r++)
                #pragma unroll
                for (int c = 0; c < 4; c++) s[r][c] = 0.f;
            #pragma unroll 8
            for (int q16 = 0; q16 < 16; q16++) {
                float4 qv[4], kv[4];
                #pragma unroll
                for (int r = 0; r < 4; r++)
                    qv[r] = *(const float4*)&Qs[(rb + il+4*r)*68 + q16*4];
                #pragma unroll
                for (int c = 0; c < 4; c++)
                    kv[c] = *(const float4*)&Ks[(32*w + jl + 8*c)*68 + q16*4];
                #pragma unroll
                for (int r = 0; r < 4; r++)
                    #pragma unroll
                    for (int c = 0; c < 4; c++)
                        s[r][c] += qv[r].x*kv[c].x + qv[r].y*kv[c].y
                                 + qv[r].z*kv[c].z + qv[r].w*kv[c].w;
            }
            #pragma unroll
            for (int r = 0; r < 4; r++) {
                int i = il + 4*r;
                #pragma unroll
                for (int c = 0; c < 4; c++) {
                    int j = 32*w + jl + 8*c;
                    int rel = spatial[(b*TT + i0 + rb + i)*TT + j];
                    Ss[i*260 + j] = s[r][c] + QRs[(rb+i)*68 + rel];
                }
            }
        }
        __syncthreads();

        // softmax: warp w handles rows 2w, 2w+1 of Ss
        #pragma unroll
        for (int rr = 0; rr < 2; rr++) {
            int ii = w*2 + rr;
            float vals[8];
            float vmax = -1e30f;
            #pragma unroll
            for (int k = 0; k < 8; k++) {
                vals[k] = Ss[ii*260 + lane + 32*k];
                vmax = fmaxf(vmax, vals[k]);
            }
            #pragma unroll
            for (int o = 16; o > 0; o >>= 1)
                vmax = fmaxf(vmax, __shfl_xor_sync(0xffffffff, vmax, o));
            float sum = 0.f;
            #pragma unroll
            for (int k = 0; k < 8; k++) { vals[k] = __expf(vals[k] - vmax); sum += vals[k]; }
            #pragma unroll
            for (int o = 16; o > 0; o >>= 1)
                sum += __shfl_xor_sync(0xffffffff, sum, o);
            float inv = 1.f / sum;
            #pragma unroll
            for (int k = 0; k < 8; k++)
                Ss[ii*260 + lane + 32*k] = vals[k] * inv;
        }
        __syncthreads();

        // histogram into Ws rows [rb, rb+16)
        #pragma unroll 4
        for (int ii = 0; ii < 16; ii++) {
            int rel = spatial[(b*TT + i0 + rb + ii)*TT + t];
            atomicAdd(&Ws[(rb+ii)*68 + rel], Ss[ii*260 + t]);
        }

        // P6a: attn @ V partials
        {
            int jbeg = 128*jh, jend = jbeg + 128;
            #pragma unroll 4
            for (int jj = jbeg; jj < jend; jj += 2) {
                float2 p0 = *(const float2*)&Ss[ib*260 + jj];
                float2 p1 = *(const float2*)&Ss[(ib+1)*260 + jj];
                float4 v0 = *(const float4*)&Vs[jj*68 + 4*dq];
                float4 v1 = *(const float4*)&Vs[(jj+1)*68 + 4*dq];
                a6[p][0][0] += p0.x*v0.x + p0.y*v1.x;
                a6[p][0][1] += p0.x*v0.y + p0.y*v1.y;
                a6[p][0][2] += p0.x*v0.z + p0.y*v1.z;
                a6[p][0][3] += p0.x*v0.w + p0.y*v1.w;
                a6[p][1][0] += p1.x*v0.x + p1.y*v1.x;
                a6[p][1][1] += p1.x*v0.y + p1.y*v1.y;
                a6[p][1][2] += p1.x*v0.z + p1.y*v1.z;
                a6[p][1][3] += p1.x*v0.w + p1.y*v1.w;
            }
        }
        __syncthreads();   // Ss free for next pass; Ws(p) complete
    }

    // load rel_v into Ks[0:64] (Ks free after pass-B scores; sync above covers)
    {
        int q = t & 15;
        #pragma unroll
        for (int r = 0; r < 4; r++) {
            int row = (t>>4) + 16*r;
            *(float4*)&Ks[row*68 + q*4] =
                *(const float4*)&rel_v[row*DD + hd + q*4];
        }
    }
    __syncthreads();

    // P6b: += w @ rel_v ; then reduce per pass via Rs (reuse Ss region)
    float* Rs = Ss;
    for (int p = 0; p < 2; p++) {
        int rb = p * 16;
        int rbeg = 32*jh, rend = rbeg + 32;
        #pragma unroll 4
        for (int rr = rbeg; rr < rend; rr += 2) {
            float2 p0 = *(const float2*)&Ws[(rb+ib)*68 + rr];
            float2 p1 = *(const float2*)&Ws[(rb+ib+1)*68 + rr];
            float4 v0 = *(const float4*)&Ks[rr*68 + 4*dq];
            float4 v1 = *(const float4*)&Ks[(rr+1)*68 + 4*dq];
            a6[p][0][0] += p0.x*v0.x + p0.y*v1.x;
            a6[p][0][1] += p0.x*v0.y + p0.y*v1.y;
            a6[p][0][2] += p0.x*v0.z + p0.y*v1.z;
            a6[p][0][3] += p0.x*v0.w + p0.y*v1.w;
            a6[p][1][0] += p1.x*v0.x + p1.y*v1.x;
            a6[p][1][1] += p1.x*v0.y + p1.y*v1.y;
            a6[p][1][2] += p1.x*v0.z + p1.y*v1.z;
            a6[p][1][3] += p1.x*v0.w + p1.y*v1.w;
        }
        __syncthreads();
        if (jh == 0) {
            #pragma unroll
            for (int r = 0; r < 2; r++)
                *(float4*)&Rs[(ib+r)*64 + 4*dq] = *(float4*)&a6[p][r][0];
        }
        __syncthreads();
        if (jh == 1) {
            #pragma unroll
            for (int r = 0; r < 2; r++) {
                float4 o = *(const float4*)&Rs[(ib+r)*64 + 4*dq];
                o.x += a6[p][r][0]; o.y += a6[p][r][1];
                o.z += a6[p][r][2]; o.w += a6[p][r][3];
                *(float4*)&g_agg[(b*TT + i0 + rb + ib + r)*DD + hd + 4*dq] = o;
            }
        }
    }
}

// ---------------------------------------------------------------------------
// K3: out = agg @ Wo^T + bo + x -> LayerNorm -> ReLU.
// 8 rows/block -> 128 blocks (single balanced wave). (unchanged from R7)
// ---------------------------------------------------------------------------
__global__ void __launch_bounds__(256) out_kernel(
        const float* __restrict__ x,  const float* __restrict__ Wo,
        const float* __restrict__ bo, const float* __restrict__ gamma,
        const float* __restrict__ beta, float* __restrict__ out) {
    __shared__ float Agc[8*68];
    __shared__ float WoS[128*64];
    int n0 = blockIdx.x * 8;
    int t  = threadIdx.x;
    int w = t >> 5, lane = t & 31;

    int nlf = lane >> 3;
    int elf = 16*w + 2*(lane & 7);
    float acc[2][2][2];
    #pragma unroll
    for (int et = 0; et < 2; et++)
        #pragma unroll
        for (int r = 0; r < 2; r++)
            #pragma unroll
            for (int c = 0; c < 2; c++) acc[et][r][c] = 0.f;

    for (int dt = 0; dt < 4; dt++) {
        __syncthreads();
        if (t < 128) {
            int ii = t >> 4, q = t & 15;
            *(float4*)&Agc[ii*68 + q*4] =
                *(const float4*)&g_agg[(n0+ii)*DD + dt*64 + q*4];
        }
        for (int et = 0; et < 2; et++) {
            if (et == 1) __syncthreads();
            #pragma unroll
            for (int r = 0; r < 8; r++) {
                int idx = t + 256*r;
                int row = idx >> 4, q = idx & 15;
                *(float4*)&WoS[row*64 + ((q ^ (row&15))<<2)] =
                    *(const float4*)&Wo[(et*128+row)*DD + dt*64 + q*4];
            }
            __syncthreads();
            #pragma unroll 8
            for (int q16 = 0; q16 < 16; q16++) {
                float4 a[2], bfr[2];
                #pragma unroll
                for (int r = 0; r < 2; r++)
                    a[r] = *(const float4*)&Agc[(nlf+4*r)*68 + q16*4];
                #pragma unroll
                for (int c = 0; c < 2; c++) {
                    int row = elf + c;
                    bfr[c] = *(const float4*)&WoS[row*64 + ((q16 ^ (row&15))<<2)];
                }
                #pragma unroll
                for (int r = 0; r < 2; r++)
                    #pragma unroll
                    for (int c = 0; c < 2; c++)
                        acc[et][r][c] += a[r].x*bfr[c].x + a[r].y*bfr[c].y
                                       + a[r].z*bfr[c].z + a[r].w*bfr[c].w;
            }
            __syncthreads();
        }
    }

    float* OutS = WoS;
    #pragma unroll
    for (int et = 0; et < 2; et++)
        #pragma unroll
        for (int r = 0; r < 2; r++) {
            int n = nlf + 4*r;
            #pragma unroll
            for (int c = 0; c < 2; c++) {
                int e = et*128 + elf + c;
                OutS[n*256 + e] = acc[et][r][c] + bo[e] + x[(n0+n)*DD + e];
            }
        }
    __syncthreads();

    {
        int ii = w;
        float vals[8];
        float sum = 0.f, sq = 0.f;
        #pragma unroll
        for (int k = 0; k < 8; k++) {
            vals[k] = OutS[ii*256 + lane + 32*k];
            sum += vals[k]; sq += vals[k]*vals[k];
        }
        #pragma unroll
        for (int o = 16; o > 0; o >>= 1) {
            sum += __shfl_xor_sync(0xffffffff, sum, o);
            sq  += __shfl_xor_sync(0xffffffff, sq,  o);
        }
        float mu  = sum * (1.f/256.f);
        float var = sq  * (1.f/256.f) - mu*mu;
        float inv = rsqrtf(var + 1e-5f);
        #pragma unroll
        for (int k = 0; k < 8; k++) {
            int e = lane + 32*k;
            float y = (vals[k] - mu) * inv * gamma[e] + beta[e];
            out[(n0+ii)*DD + e] = fmaxf(y, 0.f);
        }
    }
}

extern "C" void kernel_launch(void* const* d_in, const int* in_sizes, int n_in,
                              void* d_out, int out_size) {
    const float* x       = (const float*)d_in[0];
    const int*   spatial = (const int*)  d_in[1];
    const float* Wq      = (const float*)d_in[2];
    const float* bq      = (const float*)d_in[3];
    const float* Wk      = (const float*)d_in[4];
    const float* bk      = (const float*)d_in[5];
    const float* Wv      = (const float*)d_in[6];
    const float* bv      = (const float*)d_in[7];
    const float* rel_k   = (const float*)d_in[8];
    const float* rel_v   = (const float*)d_in[9];
    const float* Wo      = (const float*)d_in[10];
    const float* bo      = (const float*)d_in[11];
    const float* gamma   = (const float*)d_in[12];
    const float* beta    = (const float*)d_in[13];
    float* out = (float*)d_out;

    // Non-stream runtime call: executes immediately even under capture;
    // idempotent & deterministic.
    cudaFuncSetAttribute(attn_kernel,
                         cudaFuncAttributeMaxDynamicSharedMemorySize,
                         ATTN_SMEM_FLOATS * (int)sizeof(float));

    qkv_kernel <<<dim3(16, 8), 128>>>(x, Wq, Wk, Wv, bq, bk, bv);
    attn_kernel<<<dim3(8, 4, 4), 256, ATTN_SMEM_FLOATS * sizeof(float)>>>(
        spatial, rel_k, rel_v);
    out_kernel <<<128, 256>>>(x, Wo, bo, gamma, beta, out);
}

// round 13
// speedup vs baseline: 1.3279x; 1.3279x over previous
#include <cuda_runtime.h>

#define BB 4
#define TT 256
#define DD 256
#define HH 4
#define DKK 64
#define NREL 64
#define NT (BB*TT)   // 1024

typedef unsigned long long ull;

__device__ float g_q[NT*DD];
__device__ float g_k[NT*DD];
__device__ float g_v[NT*DD];
__device__ float g_agg[NT*DD];

// ---- packed f32x2 helpers (Blackwell FFMA2) --------------------------------
__device__ __forceinline__ void ffma2(ull& acc, ull a, ull b) {
    asm("fma.rn.f32x2 %0, %1, %2, %0;" : "+l"(acc) : "l"(a), "l"(b));
}
__device__ __forceinline__ float f32x2_sum(ull v) {
    float lo, hi;
    asm("mov.b64 {%0,%1}, %2;" : "=f"(lo), "=f"(hi) : "l"(v));
    return lo + hi;
}
__device__ __forceinline__ float2 f32x2_unpack(ull v) {
    float2 f;
    asm("mov.b64 {%0,%1}, %2;" : "=f"(f.x), "=f"(f.y) : "l"(v));
    return f;
}
__device__ __forceinline__ ull f32x2_bcast(float x) {
    ull v;
    asm("mov.b64 %0, {%1,%1};" : "=l"(v) : "f"(x));
    return v;
}

// ---------------------------------------------------------------------------
// K1: QKV projection (R7 config: 64n x 32e, grid 16x8x3=384, 128 thr).
// Inner loop in f32x2: 32 FFMA2 per q16 instead of 64 FFMA.
// ---------------------------------------------------------------------------
__global__ void __launch_bounds__(128) qkv_kernel(
        const float* __restrict__ x,
        const float* __restrict__ Wq, const float* __restrict__ Wk,
        const float* __restrict__ Wv,
        const float* __restrict__ bq, const float* __restrict__ bk,
        const float* __restrict__ bv) {
    __shared__ float As[64*64];
    __shared__ float Bs[32*64];
    int n0 = blockIdx.x * 64;
    int e0 = blockIdx.y * 32;
    const float* W; const float* bias; float* out;
    if (blockIdx.z == 0)      { W = Wq; bias = bq; out = g_q; }
    else if (blockIdx.z == 1) { W = Wk; bias = bk; out = g_k; }
    else                      { W = Wv; bias = bv; out = g_v; }

    int t  = threadIdx.x;
    int el = t & 7;          // e = e0 + el + 8j, j=0..3
    int nl = t >> 3;         // n = n0 + nl + 16i, i=0..3
    ull acc2[4][4];
    #pragma unroll
    for (int i = 0; i < 4; i++)
        #pragma unroll
        for (int j = 0; j < 4; j++) acc2[i][j] = 0ull;

    int lrow = t >> 4;       // 0..7
    int lq   = t & 15;       // quad 0..15

    for (int d0 = 0; d0 < DD; d0 += 64) {
        __syncthreads();
        #pragma unroll
        for (int r = 0; r < 8; r++) {
            int row = lrow + 8*r;
            *(float4*)&As[row*64 + ((lq ^ (row&15))<<2)] =
                *(const float4*)&x[(n0+row)*DD + d0 + lq*4];
        }
        #pragma unroll
        for (int r = 0; r < 4; r++) {
            int row = lrow + 8*r;
            *(float4*)&Bs[row*64 + ((lq ^ (row&15))<<2)] =
                *(const float4*)&W[(e0+row)*DD + d0 + lq*4];
        }
        __syncthreads();
        #pragma unroll 16
        for (int q16 = 0; q16 < 16; q16++) {
            ulonglong2 a[4], b[4];
            #pragma unroll
            for (int i = 0; i < 4; i++) {
                int row = nl + 16*i;
                a[i] = *(const ulonglong2*)&As[row*64 + ((q16 ^ (row&15))<<2)];
            }
            #pragma unroll
            for (int j = 0; j < 4; j++) {
                int row = el + 8*j;
                b[j] = *(const ulonglong2*)&Bs[row*64 + ((q16 ^ (row&15))<<2)];
            }
            #pragma unroll
            for (int i = 0; i < 4; i++)
                #pragma unroll
                for (int j = 0; j < 4; j++) {
                    ffma2(acc2[i][j], a[i].x, b[j].x);
                    ffma2(acc2[i][j], a[i].y, b[j].y);
                }
        }
    }
    #pragma unroll
    for (int i = 0; i < 4; i++) {
        int n = n0 + nl + 16*i;
        #pragma unroll
        for (int j = 0; j < 4; j++) {
            int e = e0 + el + 8*j;
            out[n*DD + e] = f32x2_sum(acc2[i][j]) + bias[e];
        }
    }
}

// ---------------------------------------------------------------------------
// K2: fused attention (R7 config: 16-row tiles, grid (16,4,4)=256, 256 thr,
// 99KB dynamic smem). Hot loops in f32x2.
// ---------------------------------------------------------------------------
#define ATTN_SMEM_FLOATS (256*68 + 16*68 + 16*68 + 16*260 + 16*68)
// layout: KVs[256*68] | Qs[16*68] | QRs[16*68] | Ss[16*260] | Ws[16*68]

extern __shared__ float sm[];

__global__ void __launch_bounds__(256) attn_kernel(
        const int*  __restrict__ spatial,
        const float* __restrict__ rel_k,
        const float* __restrict__ rel_v) {
    float* KVs = sm;
    float* Qs  = KVs + 256*68;
    float* QRs = Qs  + 16*68;
    float* Ss  = QRs + 16*68;
    float* Ws  = Ss  + 16*260;

    int it = blockIdx.x, h = blockIdx.y, b = blockIdx.z;
    int i0 = it * 16;
    int t  = threadIdx.x;
    int hd = h * DKK;
    int w = t >> 5, lane = t & 31;

    // P0: Q tile [16x64] + rel_k [64x64] + zero Ws
    {
        int ii = t >> 4, q = t & 15;
        *(float4*)&Qs[ii*68 + q*4] =
            *(const float4*)&g_q[(b*TT + i0 + ii)*DD + hd + q*4];
        #pragma unroll
        for (int r = 0; r < 4; r++) {
            int row = (t>>4) + 16*r;
            *(float4*)&KVs[row*68 + q*4] =
                *(const float4*)&rel_k[row*DD + hd + q*4];
        }
    }
    for (int idx = t; idx < 16*68; idx += 256) Ws[idx] = 0.f;
    __syncthreads();

    // P2: qr[ii][rel] = <Q_ii, rel_k[rel]>
    #pragma unroll
    for (int rr = 0; rr < 4; rr++) {
        int o = t + 256*rr;
        int ii = o >> 6, rel = o & 63;
        ull s2 = 0ull;
        #pragma unroll
        for (int q16 = 0; q16 < 16; q16++) {
            ulonglong2 qv = *(const ulonglong2*)&Qs[ii*68 + q16*4];
            ulonglong2 kv = *(const ulonglong2*)&KVs[rel*68 + q16*4];
            ffma2(s2, qv.x, kv.x);
            ffma2(s2, qv.y, kv.y);
        }
        QRs[ii*68 + rel] = f32x2_sum(s2);
    }
    __syncthreads();

    // load full K [256x64]
    {
        int q = t & 15;
        #pragma unroll
        for (int r = 0; r < 16; r++) {
            int row = (t>>4) + 16*r;
            *(float4*)&KVs[row*68 + q*4] =
                *(const float4*)&g_k[(b*TT + row)*DD + hd + q*4];
        }
    }
    __syncthreads();

    // P3: scores. warp w owns j in [32w,32w+32); i = il+4r, j = 32w+jl+8c.
    {
        int jl = lane & 7, il = lane >> 3;
        ull s2[4][4];
        #pragma unroll
        for (int r = 0; r < 4; r++)
            #pragma unroll
            for (int c = 0; c < 4; c++) s2[r][c] = 0ull;
        #pragma unroll 8
        for (int q16 = 0; q16 < 16; q16++) {
            ulonglong2 qv[4], kv[4];
            #pragma unroll
            for (int r = 0; r < 4; r++)
                qv[r] = *(const ulonglong2*)&Qs[(il+4*r)*68 + q16*4];
            #pragma unroll
            for (int c = 0; c < 4; c++)
                kv[c] = *(const ulonglong2*)&KVs[(32*w + jl + 8*c)*68 + q16*4];
            #pragma unroll
            for (int r = 0; r < 4; r++)
                #pragma unroll
                for (int c = 0; c < 4; c++) {
                    ffma2(s2[r][c], qv[r].x, kv[c].x);
                    ffma2(s2[r][c], qv[r].y, kv[c].y);
                }
        }
        #pragma unroll
        for (int r = 0; r < 4; r++) {
            int i = il + 4*r;
            #pragma unroll
            for (int c = 0; c < 4; c++) {
                int j = 32*w + jl + 8*c;
                int rel = spatial[(b*TT + i0 + i)*TT + j];
                Ss[i*260 + j] = (f32x2_sum(s2[r][c]) + QRs[i*68 + rel]) * 0.125f;
            }
        }
    }
    __syncthreads();

    // load V over K (all warps past P3 due to sync above)
    {
        int q = t & 15;
        #pragma unroll
        for (int r = 0; r < 16; r++) {
            int row = (t>>4) + 16*r;
            *(float4*)&KVs[row*68 + q*4] =
                *(const float4*)&g_v[(b*TT + row)*DD + hd + q*4];
        }
    }

    // P4: softmax, warp w handles rows 2w, 2w+1
    #pragma unroll
    for (int rr = 0; rr < 2; rr++) {
        int ii = w*2 + rr;
        float vals[8];
        float vmax = -1e30f;
        #pragma unroll
        for (int k = 0; k < 8; k++) {
            vals[k] = Ss[ii*260 + lane + 32*k];
            vmax = fmaxf(vmax, vals[k]);
        }
        #pragma unroll
        for (int o = 16; o > 0; o >>= 1)
            vmax = fmaxf(vmax, __shfl_xor_sync(0xffffffff, vmax, o));
        float sum = 0.f;
        #pragma unroll
        for (int k = 0; k < 8; k++) { vals[k] = __expf(vals[k] - vmax); sum += vals[k]; }
        #pragma unroll
        for (int o = 16; o > 0; o >>= 1)
            sum += __shfl_xor_sync(0xffffffff, sum, o);
        float inv = 1.f / sum;
        #pragma unroll
        for (int k = 0; k < 8; k++)
            Ss[ii*260 + lane + 32*k] = vals[k] * inv;
    }
    __syncthreads();   // covers V load + softmax completion

    // P5: relation histogram (thread t owns column j=t)
    #pragma unroll 4
    for (int ii = 0; ii < 16; ii++) {
        int rel = spatial[(b*TT + i0 + ii)*TT + t];
        atomicAdd(&Ws[ii*68 + rel], Ss[ii*260 + t]);
    }

    // P6a: agg partial = attn @ V, packed over d. warp: iy=w&3, jh=w>>2.
    int iy = w & 3, jh = w >> 2;
    int il2 = lane >> 4, dq = lane & 15;
    int ib = 4*iy + 2*il2;
    ull a2[2][2];    // [row 0/1][d-pair 0/1]; lo=d0/d2, hi=d1/d3
    a2[0][0] = a2[0][1] = a2[1][0] = a2[1][1] = 0ull;
    {
        int jbeg = 128*jh, jend = jbeg + 128;
        #pragma unroll 4
        for (int jj = jbeg; jj < jend; jj += 2) {
            float2 p0 = *(const float2*)&Ss[ib*260 + jj];
            float2 p1 = *(const float2*)&Ss[(ib+1)*260 + jj];
            ull pp00 = f32x2_bcast(p0.x), pp01 = f32x2_bcast(p0.y);
            ull pp10 = f32x2_bcast(p1.x), pp11 = f32x2_bcast(p1.y);
            ulonglong2 v0 = *(const ulonglong2*)&KVs[jj*68 + 4*dq];
            ulonglong2 v1 = *(const ulonglong2*)&KVs[(jj+1)*68 + 4*dq];
            ffma2(a2[0][0], pp00, v0.x); ffma2(a2[0][1], pp00, v0.y);
            ffma2(a2[0][0], pp01, v1.x); ffma2(a2[0][1], pp01, v1.y);
            ffma2(a2[1][0], pp10, v0.x); ffma2(a2[1][1], pp10, v0.y);
            ffma2(a2[1][0], pp11, v1.x); ffma2(a2[1][1], pp11, v1.y);
        }
    }
    __syncthreads();   // Ws complete (P5), KVs free

    // load rel_v into KVs[0:64]
    {
        int q = t & 15;
        #pragma unroll
        for (int r = 0; r < 4; r++) {
            int row = (t>>4) + 16*r;
            *(float4*)&KVs[row*68 + q*4] =
                *(const float4*)&rel_v[row*DD + hd + q*4];
        }
    }
    __syncthreads();

    // P6b: += w @ rel_v, packed over d
    {
        int rbeg = 32*jh, rend = rbeg + 32;
        #pragma unroll 4
        for (int rr = rbeg; rr < rend; rr += 2) {
            float2 p0 = *(const float2*)&Ws[ib*68 + rr];
            float2 p1 = *(const float2*)&Ws[(ib+1)*68 + rr];
            ull pp00 = f32x2_bcast(p0.x), pp01 = f32x2_bcast(p0.y);
            ull pp10 = f32x2_bcast(p1.x), pp11 = f32x2_bcast(p1.y);
            ulonglong2 v0 = *(const ulonglong2*)&KVs[rr*68 + 4*dq];
            ulonglong2 v1 = *(const ulonglong2*)&KVs[(rr+1)*68 + 4*dq];
            ffma2(a2[0][0], pp00, v0.x); ffma2(a2[0][1], pp00, v0.y);
            ffma2(a2[0][0], pp01, v1.x); ffma2(a2[0][1], pp01, v1.y);
            ffma2(a2[1][0], pp10, v0.x); ffma2(a2[1][1], pp10, v0.y);
            ffma2(a2[1][0], pp11, v1.x); ffma2(a2[1][1], pp11, v1.y);
        }
    }

    // reduce two j-halves via shared (reuse Qs as 16x64 buffer)
    float* Rs = Qs;
    if (jh == 0) {
        #pragma unroll
        for (int r = 0; r < 2; r++) {
            float2 lo = f32x2_unpack(a2[r][0]);
            float2 hi = f32x2_unpack(a2[r][1]);
            float4 o = make_float4(lo.x, lo.y, hi.x, hi.y);
            *(float4*)&Rs[(ib+r)*64 + 4*dq] = o;
        }
    }
    __syncthreads();
    if (jh == 1) {
        #pragma unroll
        for (int r = 0; r < 2; r++) {
            float4 o = *(const float4*)&Rs[(ib+r)*64 + 4*dq];
            float2 lo = f32x2_unpack(a2[r][0]);
            float2 hi = f32x2_unpack(a2[r][1]);
            o.x += lo.x; o.y += lo.y; o.z += hi.x; o.w += hi.y;
            *(float4*)&g_agg[(b*TT + i0 + ib + r)*DD + hd + 4*dq] = o;
        }
    }
}

// ---------------------------------------------------------------------------
// K3: out = agg @ Wo^T + bo + x -> LayerNorm -> ReLU. 8 rows/block, 128 blk.
// GEMM inner loop in f32x2.
// ---------------------------------------------------------------------------
__global__ void __launch_bounds__(256) out_kernel(
        const float* __restrict__ x,  const float* __restrict__ Wo,
        const float* __restrict__ bo, const float* __restrict__ gamma,
        const float* __restrict__ beta, float* __restrict__ out) {
    __shared__ float Agc[8*68];
    __shared__ float WoS[128*64];
    int n0 = blockIdx.x * 8;
    int t  = threadIdx.x;
    int w = t >> 5, lane = t & 31;

    int nlf = lane >> 3;
    int elf = 16*w + 2*(lane & 7);
    ull acc2[2][2][2];
    #pragma unroll
    for (int et = 0; et < 2; et++)
        #pragma unroll
        for (int r = 0; r < 2; r++)
            #pragma unroll
            for (int c = 0; c < 2; c++) acc2[et][r][c] = 0ull;

    for (int dt = 0; dt < 4; dt++) {
        __syncthreads();
        if (t < 128) {
            int ii = t >> 4, q = t & 15;
            *(float4*)&Agc[ii*68 + q*4] =
                *(const float4*)&g_agg[(n0+ii)*DD + dt*64 + q*4];
        }
        for (int et = 0; et < 2; et++) {
            if (et == 1) __syncthreads();
            #pragma unroll
            for (int r = 0; r < 8; r++) {
                int idx = t + 256*r;
                int row = idx >> 4, q = idx & 15;
                *(float4*)&WoS[row*64 + ((q ^ (row&15))<<2)] =
                    *(const float4*)&Wo[(et*128+row)*DD + dt*64 + q*4];
            }
            __syncthreads();
            #pragma unroll 8
            for (int q16 = 0; q16 < 16; q16++) {
                ulonglong2 a[2], bfr[2];
                #pragma unroll
                for (int r = 0; r < 2; r++)
                    a[r] = *(const ulonglong2*)&Agc[(nlf+4*r)*68 + q16*4];
                #pragma unroll
                for (int c = 0; c < 2; c++) {
                    int row = elf + c;
                    bfr[c] = *(const ulonglong2*)&WoS[row*64 + ((q16 ^ (row&15))<<2)];
                }
                #pragma unroll
                for (int r = 0; r < 2; r++)
                    #pragma unroll
                    for (int c = 0; c < 2; c++) {
                        ffma2(acc2[et][r][c], a[r].x, bfr[c].x);
                        ffma2(acc2[et][r][c], a[r].y, bfr[c].y);
                    }
            }
            __syncthreads();
        }
    }

    float* OutS = WoS;
    #pragma unroll
    for (int et = 0; et < 2; et++)
        #pragma unroll
        for (int r = 0; r < 2; r++) {
            int n = nlf + 4*r;
            #pragma unroll
            for (int c = 0; c < 2; c++) {
                int e = et*128 + elf + c;
                OutS[n*256 + e] = f32x2_sum(acc2[et][r][c]) + bo[e]
                                + x[(n0+n)*DD + e];
            }
        }
    __syncthreads();

    {
        int ii = w;
        float vals[8];
        float sum = 0.f, sq = 0.f;
        #pragma unroll
        for (int k = 0; k < 8; k++) {
            vals[k] = OutS[ii*256 + lane + 32*k];
            sum += vals[k]; sq += vals[k]*vals[k];
        }
        #pragma unroll
        for (int o = 16; o > 0; o >>= 1) {
            sum += __shfl_xor_sync(0xffffffff, sum, o);
            sq  += __shfl_xor_sync(0xffffffff, sq,  o);
        }
        float mu  = sum * (1.f/256.f);
        float var = sq  * (1.f/256.f) - mu*mu;
        float inv = rsqrtf(var + 1e-5f);
        #pragma unroll
        for (int k = 0; k < 8; k++) {
            int e = lane + 32*k;
            float y = (vals[k] - mu) * inv * gamma[e] + beta[e];
            out[(n0+ii)*DD + e] = fmaxf(y, 0.f);
        }
    }
}

extern "C" void kernel_launch(void* const* d_in, const int* in_sizes, int n_in,
                              void* d_out, int out_size) {
    const float* x       = (const float*)d_in[0];
    const int*   spatial = (const int*)  d_in[1];
    const float* Wq      = (const float*)d_in[2];
    const float* bq      = (const float*)d_in[3];
    const float* Wk      = (const float*)d_in[4];
    const float* bk      = (const float*)d_in[5];
    const float* Wv      = (const float*)d_in[6];
    const float* bv      = (const float*)d_in[7];
    const float* rel_k   = (const float*)d_in[8];
    const float* rel_v   = (const float*)d_in[9];
    const float* Wo      = (const float*)d_in[10];
    const float* bo      = (const float*)d_in[11];
    const float* gamma   = (const float*)d_in[12];
    const float* beta    = (const float*)d_in[13];
    float* out = (float*)d_out;

    // Non-stream runtime call: executes immediately even under capture;
    // idempotent & deterministic.
    cudaFuncSetAttribute(attn_kernel,
                         cudaFuncAttributeMaxDynamicSharedMemorySize,
                         ATTN_SMEM_FLOATS * (int)sizeof(float));

    qkv_kernel <<<dim3(16, 8, 3), 128>>>(x, Wq, Wk, Wv, bq, bk, bv);
    attn_kernel<<<dim3(16, 4, 4), 256, ATTN_SMEM_FLOATS * sizeof(float)>>>(
        spatial, rel_k, rel_v);
    out_kernel <<<128, 256>>>(x, Wo, bo, gamma, beta, out);
}